// round 14
// baseline (speedup 1.0000x reference)
#include <cuda_runtime.h>

#define B_SZ   512
#define F_SZ   512
#define NK     50
#define DK     16
#define NCOL   (NK*DK)     // 800
#define OUTW   (F_SZ + NK) // 562
#define KSPLIT 8
#define KCHUNK (F_SZ / KSPLIT)   // 64
#define ACT_SZ (B_SZ * NCOL)

__device__ float g_act_part[KSPLIT * ACT_SZ];  // split-K partials (m-major)
__device__ float g_act_T[NCOL * B_SZ];         // reduced, TRANSPOSED: [n][m]

// 10 tile-pairs (I<=J) over 4 row-tiles of 128
__constant__ int PAIR_I[10] = {0,0,0,0,1,1,1,2,2,3};
__constant__ int PAIR_J[10] = {0,1,2,3,1,2,3,2,3,3};

// ---------------------------------------------------------------------------
// packed f32x2 helpers (FFMA2 — only reachable via PTX fma.rn.f32x2)
// ---------------------------------------------------------------------------
__device__ __forceinline__ unsigned long long ffma2(unsigned long long a,
                                                    unsigned long long b,
                                                    unsigned long long c) {
    unsigned long long d;
    asm("fma.rn.f32x2 %0, %1, %2, %3;" : "=l"(d) : "l"(a), "l"(b), "l"(c));
    return d;
}
__device__ __forceinline__ unsigned long long pack2(float x) {
    unsigned long long d;
    asm("mov.b64 %0, {%1, %1};" : "=l"(d) : "r"(__float_as_uint(x)));
    return d;
}
__device__ __forceinline__ unsigned long long pack2f(float lo, float hi) {
    unsigned long long d;
    asm("mov.b64 %0, {%1, %2};" : "=l"(d) : "r"(__float_as_uint(lo)), "r"(__float_as_uint(hi)));
    return d;
}
#define ONE2  0x3F8000003F800000ULL
#define ABSM2 0x7FFFFFFF7FFFFFFFULL

// ---------------------------------------------------------------------------
// GEMM split-K (R13 version; output stores widened to STG.64).
// ---------------------------------------------------------------------------
__global__ __launch_bounds__(256, 6) void gemm_kernel(const float* __restrict__ A,
                                                      const float* __restrict__ Bm) {
    __shared__ float As[64][64];   // As[m][k]
    __shared__ float Bs[64][64];   // Bs[k][n]

    const int tid = threadIdx.x;
    const int m0  = blockIdx.y * 64;
    const int n0  = blockIdx.x * 64;
    const int kc  = blockIdx.z;
    const int kbeg = kc * KCHUNK;
    float* out = g_act_part + kc * ACT_SZ;

    #pragma unroll
    for (int p = 0; p < 4; p++) {
        int idx = tid + p * 256;
        int r  = idx >> 4;
        int c4 = idx & 15;
        float4 v = *(const float4*)(A + (m0 + r) * F_SZ + kbeg + c4 * 4);
        *(float4*)&As[r][c4 * 4] = v;
    }
    #pragma unroll
    for (int p = 0; p < 4; p++) {
        int idx = tid + p * 256;
        int r  = idx >> 4;
        int c4 = idx & 15;
        int n  = n0 + c4 * 4;
        float4 v = (n < NCOL) ? *(const float4*)(Bm + (kbeg + r) * NCOL + n)
                              : make_float4(0.f, 0.f, 0.f, 0.f);
        *(float4*)&Bs[r][c4 * 4] = v;
    }
    __syncthreads();

    const int ty = tid >> 4;
    const int tx = tid & 15;
    unsigned long long acc2[4][2] = {};

    #pragma unroll 8
    for (int kk = 0; kk < 64; kk++) {
        unsigned long long b01 = *(const unsigned long long*)&Bs[kk][tx * 4 + 0];
        unsigned long long b23 = *(const unsigned long long*)&Bs[kk][tx * 4 + 2];
        #pragma unroll
        for (int i = 0; i < 4; i++) {
            unsigned long long a2 = pack2(As[ty * 4 + i][kk]);
            acc2[i][0] = ffma2(a2, b01, acc2[i][0]);
            acc2[i][1] = ffma2(a2, b23, acc2[i][1]);
        }
    }

    #pragma unroll
    for (int i = 0; i < 4; i++) {
        int m = m0 + ty * 4 + i;
        #pragma unroll
        for (int q = 0; q < 2; q++) {
            int n = n0 + tx * 4 + q * 2;
            if (n < NCOL)   // 8B-aligned (n even): single STG.64
                *(unsigned long long*)&out[m * NCOL + n] = acc2[i][q];
        }
    }
}

// ---------------------------------------------------------------------------
// MERGED: reduce+transpose (blocks 0..399) and prep_out (blocks 400..961).
// ---------------------------------------------------------------------------
__global__ __launch_bounds__(256) void epilogue_kernel(const float* __restrict__ x,
                                                       float* __restrict__ out) {
    const int bx = blockIdx.x;
    if (bx < 400) {
        __shared__ float t[32][33];
        const int tm0 = (bx & 15) * 32;
        const int tn0 = (bx >> 4) * 32;
        const int c = threadIdx.x & 31;
        const int r = threadIdx.x >> 5;

        #pragma unroll
        for (int q = 0; q < 4; q++) {
            int mi = r * 4 + q;
            int idx = (tm0 + mi) * NCOL + tn0 + c;
            float s = 0.0f;
            #pragma unroll
            for (int p = 0; p < KSPLIT; p++) s += g_act_part[p * ACT_SZ + idx];
            t[mi][c] = s;
        }
        __syncthreads();
        #pragma unroll
        for (int q = 0; q < 4; q++) {
            int ni = r * 4 + q;
            g_act_T[(tn0 + ni) * B_SZ + tm0 + c] = t[c][ni];
        }
    } else {
        int idx = (bx - 400) * 256 + threadIdx.x;
        int b = idx / 281, j = idx - b * 281;
        float2 v;
        if (j < 256) v = ((const float2*)(x + (size_t)b * F_SZ))[j];
        else         v = make_float2(0.0f, 0.0f);
        ((float2*)(out + (size_t)b * OUTW))[j] = v;
    }
}

// ---------------------------------------------------------------------------
// Symmetric pairwise, PACKED f32x2 core. Structure identical to R8 winner;
// inner math: 8 ffma2 diffs (v*1 + (-a)) + 16 LOP3 abs (alu pipe) + 7 ffma2
// tree + scalar finish. fma-pipe work ~halved vs scalar FADD version.
// grid = (40, 50), block = 128.
// ---------------------------------------------------------------------------
__global__ __launch_bounds__(128) void pairwise_kernel(float* __restrict__ out) {
    __shared__ float sJ[32][16];        // 2 KB, rows 64B-aligned
    __shared__ float e_smem[128][33];   // 16.9 KB padded
    __shared__ float scol[4][32];

    const int bx   = blockIdx.x;
    const int pair = bx >> 2;
    const int c0   = (bx & 3) * 32;
    const int I = PAIR_I[pair];
    const int J = PAIR_J[pair];
    const int k   = blockIdx.y;
    const int tid = threadIdx.x;

    {
        int d  = tid >> 3;
        int m4 = (tid & 7) * 4;
        float4 v = *(const float4*)(g_act_T + (k * DK + d) * B_SZ + J * 128 + c0 + m4);
        sJ[m4 + 0][d] = v.x;
        sJ[m4 + 1][d] = v.y;
        sJ[m4 + 2][d] = v.z;
        sJ[m4 + 3][d] = v.w;
    }

    // own row, pre-negated and packed into 8 x f32x2
    unsigned long long an[8];
    const int rowB = I * 128 + tid;
    #pragma unroll
    for (int q = 0; q < 8; q++) {
        float lo = g_act_T[(k * DK + 2*q    ) * B_SZ + rowB];
        float hi = g_act_T[(k * DK + 2*q + 1) * B_SZ + rowB];
        an[q] = pack2f(-lo, -hi);
    }
    __syncthreads();

    const bool diag = (I == J);
    float rowAcc = 0.0f;

    #pragma unroll 4
    for (int b2 = 0; b2 < 32; b2++) {
        const unsigned long long* vp = (const unsigned long long*)sJ[b2]; // broadcast
        unsigned long long d0 = ffma2(vp[0], ONE2, an[0]) & ABSM2;
        unsigned long long d1 = ffma2(vp[1], ONE2, an[1]) & ABSM2;
        unsigned long long d2 = ffma2(vp[2], ONE2, an[2]) & ABSM2;
        unsigned long long d3 = ffma2(vp[3], ONE2, an[3]) & ABSM2;
        unsigned long long d4 = ffma2(vp[4], ONE2, an[4]) & ABSM2;
        unsigned long long d5 = ffma2(vp[5], ONE2, an[5]) & ABSM2;
        unsigned long long d6 = ffma2(vp[6], ONE2, an[6]) & ABSM2;
        unsigned long long d7 = ffma2(vp[7], ONE2, an[7]) & ABSM2;
        unsigned long long t0 = ffma2(d0, ONE2, d1);
        unsigned long long t1 = ffma2(d2, ONE2, d3);
        unsigned long long t2 = ffma2(d4, ONE2, d5);
        unsigned long long t3 = ffma2(d6, ONE2, d7);
        t0 = ffma2(t0, ONE2, t1);
        t2 = ffma2(t2, ONE2, t3);
        t0 = ffma2(t0, ONE2, t2);
        float l1 = __uint_as_float((unsigned)t0)
                 + __uint_as_float((unsigned)(t0 >> 32));
        float e = __expf(-l1);
        rowAcc += e;
        if (!diag)
            e_smem[tid][b2] = e;
    }

    float* fbase = out + F_SZ + k;
    atomicAdd(fbase + (size_t)rowB * OUTW, rowAcc);

    if (!diag) {
        __syncthreads();
        const int col = tid & 31;
        const int q   = tid >> 5;
        float cs = 0.0f;
        #pragma unroll 8
        for (int r = 0; r < 32; r++)
            cs += e_smem[q * 32 + r][col];
        scol[q][col] = cs;
        __syncthreads();
        if (tid < 32) {
            float tot = scol[0][tid] + scol[1][tid]
                      + scol[2][tid] + scol[3][tid];
            atomicAdd(fbase + (size_t)(J * 128 + c0 + tid) * OUTW, tot);
        }
    }
}

// ---------------------------------------------------------------------------
extern "C" void kernel_launch(void* const* d_in, const int* in_sizes, int n_in,
                              void* d_out, int out_size) {
    const float* x = (const float*)d_in[0];
    const float* W = (const float*)d_in[1];
    float* out = (float*)d_out;

    dim3 gemm_grid((NCOL + 63) / 64, B_SZ / 64, KSPLIT);   // 13 x 8 x 8
    gemm_kernel<<<gemm_grid, 256>>>(x, W);

    epilogue_kernel<<<962, 256>>>(x, out);   // reduce_T (400) + prep (562)

    dim3 pw_grid(40, NK);                    // 40 x 50 = 2000
    pairwise_kernel<<<pw_grid, 128>>>(out);
}

// round 15
// speedup vs baseline: 1.0555x; 1.0555x over previous
#include <cuda_runtime.h>

#define B_SZ   512
#define F_SZ   512
#define NK     50
#define DK     16
#define NCOL   (NK*DK)     // 800
#define OUTW   (F_SZ + NK) // 562
#define KSPLIT 8
#define KCHUNK (F_SZ / KSPLIT)   // 64
#define ACT_SZ (B_SZ * NCOL)

__device__ float g_act_part[KSPLIT * ACT_SZ];  // split-K partials (m-major)
__device__ float g_act_T[NCOL * B_SZ];         // reduced, TRANSPOSED: [n][m]

// 10 tile-pairs (I<=J) over 4 row-tiles of 128
__constant__ int PAIR_I[10] = {0,0,0,0,1,1,1,2,2,3};
__constant__ int PAIR_J[10] = {0,1,2,3,1,2,3,2,3,3};

// ---------------------------------------------------------------------------
// packed f32x2 helpers (FFMA2 via PTX) — used by GEMM only
// ---------------------------------------------------------------------------
__device__ __forceinline__ unsigned long long ffma2(unsigned long long a,
                                                    unsigned long long b,
                                                    unsigned long long c) {
    unsigned long long d;
    asm("fma.rn.f32x2 %0, %1, %2, %3;" : "=l"(d) : "l"(a), "l"(b), "l"(c));
    return d;
}
__device__ __forceinline__ unsigned long long pack2(float x) {
    unsigned long long d;
    asm("mov.b64 %0, {%1, %1};" : "=l"(d) : "r"(__float_as_uint(x)));
    return d;
}

// ---------------------------------------------------------------------------
// GEMM split-K (R13 version, unchanged — proven 20.2us).
// ---------------------------------------------------------------------------
__global__ __launch_bounds__(256, 6) void gemm_kernel(const float* __restrict__ A,
                                                      const float* __restrict__ Bm) {
    __shared__ float As[64][64];   // As[m][k]
    __shared__ float Bs[64][64];   // Bs[k][n]

    const int tid = threadIdx.x;
    const int m0  = blockIdx.y * 64;
    const int n0  = blockIdx.x * 64;
    const int kc  = blockIdx.z;
    const int kbeg = kc * KCHUNK;
    float* out = g_act_part + kc * ACT_SZ;

    #pragma unroll
    for (int p = 0; p < 4; p++) {
        int idx = tid + p * 256;
        int r  = idx >> 4;
        int c4 = idx & 15;
        float4 v = *(const float4*)(A + (m0 + r) * F_SZ + kbeg + c4 * 4);
        *(float4*)&As[r][c4 * 4] = v;
    }
    #pragma unroll
    for (int p = 0; p < 4; p++) {
        int idx = tid + p * 256;
        int r  = idx >> 4;
        int c4 = idx & 15;
        int n  = n0 + c4 * 4;
        float4 v = (n < NCOL) ? *(const float4*)(Bm + (kbeg + r) * NCOL + n)
                              : make_float4(0.f, 0.f, 0.f, 0.f);
        *(float4*)&Bs[r][c4 * 4] = v;
    }
    __syncthreads();

    const int ty = tid >> 4;
    const int tx = tid & 15;
    unsigned long long acc2[4][2] = {};

    #pragma unroll 8
    for (int kk = 0; kk < 64; kk++) {
        unsigned long long b01 = *(const unsigned long long*)&Bs[kk][tx * 4 + 0];
        unsigned long long b23 = *(const unsigned long long*)&Bs[kk][tx * 4 + 2];
        #pragma unroll
        for (int i = 0; i < 4; i++) {
            unsigned long long a2 = pack2(As[ty * 4 + i][kk]);
            acc2[i][0] = ffma2(a2, b01, acc2[i][0]);
            acc2[i][1] = ffma2(a2, b23, acc2[i][1]);
        }
    }

    #pragma unroll
    for (int i = 0; i < 4; i++) {
        int m = m0 + ty * 4 + i;
        #pragma unroll
        for (int q = 0; q < 2; q++) {
            int n = n0 + tx * 4 + q * 2;
            if (n < NCOL)
                *(unsigned long long*)&out[m * NCOL + n] = acc2[i][q];
        }
    }
}

// ---------------------------------------------------------------------------
// Epilogue: reduce+transpose (blocks 0..399) + ZERO feature region (400..449).
// The zeroing MUST complete before pairwise atomics -> stays in this kernel.
// ---------------------------------------------------------------------------
__global__ __launch_bounds__(256) void epilogue_kernel(float* __restrict__ out) {
    const int bx = blockIdx.x;
    if (bx < 400) {
        __shared__ float t[32][33];
        const int tm0 = (bx & 15) * 32;
        const int tn0 = (bx >> 4) * 32;
        const int c = threadIdx.x & 31;
        const int r = threadIdx.x >> 5;

        #pragma unroll
        for (int q = 0; q < 4; q++) {
            int mi = r * 4 + q;
            int idx = (tm0 + mi) * NCOL + tn0 + c;
            float s = 0.0f;
            #pragma unroll
            for (int p = 0; p < KSPLIT; p++) s += g_act_part[p * ACT_SZ + idx];
            t[mi][c] = s;
        }
        __syncthreads();
        #pragma unroll
        for (int q = 0; q < 4; q++) {
            int ni = r * 4 + q;
            g_act_T[(tn0 + ni) * B_SZ + tm0 + c] = t[c][ni];
        }
    } else {
        // zero out[:, 512:562): 512*50 = 25600 floats = 12800 float2
        int idx = (bx - 400) * 256 + threadIdx.x;    // 50*256 = 12800 exactly
        int b = idx / 25, j = idx - b * 25;          // 25 float2 per row
        ((float2*)(out + (size_t)b * OUTW + F_SZ))[j] = make_float2(0.0f, 0.0f);
    }
}

// ---------------------------------------------------------------------------
// Symmetric pairwise (R8 scalar core, proven 19.8us) + fused x-copy row.
// grid = (40, 51): y<50 -> pairwise for kernel k=y; y==50 -> copy x into
// out[:,0:512] (disjoint from feature columns; safe to run concurrently).
// ---------------------------------------------------------------------------
__global__ __launch_bounds__(128) void pairwise_kernel(const float* __restrict__ x,
                                                       float* __restrict__ out) {
    __shared__ float sJ[32][16];        // 2 KB
    __shared__ float e_smem[128][33];   // 16.9 KB padded
    __shared__ float scol[4][32];

    const int k = blockIdx.y;
    const int tid = threadIdx.x;

    if (k == NK) {
        // copy x -> out[:,0:512]: 512*256 = 131072 float2, 5120 threads
        for (int i = blockIdx.x * 128 + tid; i < 131072; i += 40 * 128) {
            int b = i >> 8, j = i & 255;
            ((float2*)(out + (size_t)b * OUTW))[j] =
                ((const float2*)(x + (size_t)b * F_SZ))[j];
        }
        return;
    }

    const int bx   = blockIdx.x;
    const int pair = bx >> 2;
    const int c0   = (bx & 3) * 32;
    const int I = PAIR_I[pair];
    const int J = PAIR_J[pair];

    {
        int d  = tid >> 3;
        int m4 = (tid & 7) * 4;
        float4 v = *(const float4*)(g_act_T + (k * DK + d) * B_SZ + J * 128 + c0 + m4);
        sJ[m4 + 0][d] = v.x;
        sJ[m4 + 1][d] = v.y;
        sJ[m4 + 2][d] = v.z;
        sJ[m4 + 3][d] = v.w;
    }

    float a[16];
    const int rowB = I * 128 + tid;
    #pragma unroll
    for (int d = 0; d < 16; d++)
        a[d] = g_act_T[(k * DK + d) * B_SZ + rowB];
    __syncthreads();

    const bool diag = (I == J);
    float rowAcc = 0.0f;

    #pragma unroll 4
    for (int b2 = 0; b2 < 32; b2++) {
        const float4* vp = (const float4*)sJ[b2];
        float4 v0 = vp[0], v1 = vp[1], v2 = vp[2], v3 = vp[3];
        float p0 = fabsf(a[0]  - v0.x) + fabsf(a[1]  - v0.y)
                 + fabsf(a[2]  - v0.z) + fabsf(a[3]  - v0.w);
        float p1 = fabsf(a[4]  - v1.x) + fabsf(a[5]  - v1.y)
                 + fabsf(a[6]  - v1.z) + fabsf(a[7]  - v1.w);
        float p2 = fabsf(a[8]  - v2.x) + fabsf(a[9]  - v2.y)
                 + fabsf(a[10] - v2.z) + fabsf(a[11] - v2.w);
        float p3 = fabsf(a[12] - v3.x) + fabsf(a[13] - v3.y)
                 + fabsf(a[14] - v3.z) + fabsf(a[15] - v3.w);
        float e = __expf(-((p0 + p1) + (p2 + p3)));
        rowAcc += e;
        if (!diag)
            e_smem[tid][b2] = e;
    }

    float* fbase = out + F_SZ + k;
    atomicAdd(fbase + (size_t)rowB * OUTW, rowAcc);

    if (!diag) {
        __syncthreads();
        const int col = tid & 31;
        const int q   = tid >> 5;
        float cs = 0.0f;
        #pragma unroll 8
        for (int r = 0; r < 32; r++)
            cs += e_smem[q * 32 + r][col];
        scol[q][col] = cs;
        __syncthreads();
        if (tid < 32) {
            float tot = scol[0][tid] + scol[1][tid]
                      + scol[2][tid] + scol[3][tid];
            atomicAdd(fbase + (size_t)(J * 128 + c0 + tid) * OUTW, tot);
        }
    }
}

// ---------------------------------------------------------------------------
extern "C" void kernel_launch(void* const* d_in, const int* in_sizes, int n_in,
                              void* d_out, int out_size) {
    const float* x = (const float*)d_in[0];
    const float* W = (const float*)d_in[1];
    float* out = (float*)d_out;

    dim3 gemm_grid((NCOL + 63) / 64, B_SZ / 64, KSPLIT);   // 13 x 8 x 8
    gemm_kernel<<<gemm_grid, 256>>>(x, W);

    epilogue_kernel<<<450, 256>>>(out);      // reduce_T (400) + zero feat (50)

    dim3 pw_grid(40, NK + 1);                // 40 x 51 (y=50: x-copy)
    pairwise_kernel<<<pw_grid, 128>>>(x, out);
}

// round 16
// speedup vs baseline: 1.1214x; 1.0624x over previous
#include <cuda_runtime.h>

#define B_SZ   512
#define F_SZ   512
#define NK     50
#define DK     16
#define NCOL   (NK*DK)     // 800
#define OUTW   (F_SZ + NK) // 562
#define KSPLIT 8
#define KCHUNK (F_SZ / KSPLIT)   // 64
#define ACT_SZ (B_SZ * NCOL)

__device__ float g_act_part[KSPLIT * ACT_SZ];  // split-K partials (m-major)
__device__ float g_act_T[NCOL * B_SZ];         // reduced, TRANSPOSED: [n][m]

// 10 tile-pairs (I<=J) over 4 row-tiles of 128
__constant__ int PAIR_I[10] = {0,0,0,0,1,1,1,2,2,3};
__constant__ int PAIR_J[10] = {0,1,2,3,1,2,3,2,3,3};

// ---------------------------------------------------------------------------
// tf32 helpers
// ---------------------------------------------------------------------------
__device__ __forceinline__ unsigned tf32_hi(float x) {
    unsigned u;
    asm("cvt.rna.tf32.f32 %0, %1;" : "=r"(u) : "f"(x));
    return u;
}
__device__ __forceinline__ void mma_tf32(float* c, const unsigned* a,
                                         unsigned b0, unsigned b1) {
    asm volatile(
        "mma.sync.aligned.m16n8k8.row.col.f32.tf32.tf32.f32 "
        "{%0,%1,%2,%3}, {%4,%5,%6,%7}, {%8,%9}, {%0,%1,%2,%3};"
        : "+f"(c[0]), "+f"(c[1]), "+f"(c[2]), "+f"(c[3])
        : "r"(a[0]), "r"(a[1]), "r"(a[2]), "r"(a[3]), "r"(b0), "r"(b1));
}

// ---------------------------------------------------------------------------
// GEMM split-K via 3xtf32 tensor-core mma.
// grid (13 n-tiles, 8 m-tiles, 8 kc) = 832 blocks, 128 threads (4 warps).
// Warp w: m-rows [16w, 16w+16), all 64 n (8 n-frags). K: 8 steps of 8.
// smem: As[m][k] + Bt[n][k], padded rows (68) -> conflict-free frag loads.
// hi/lo tf32 split done in registers: D += ah*bh + ah*bl + al*bh.
// ---------------------------------------------------------------------------
__global__ __launch_bounds__(128, 6) void gemm_kernel(const float* __restrict__ A,
                                                      const float* __restrict__ Bm) {
    __shared__ float As[64][68];   // [m][k]
    __shared__ float Bt[64][68];   // [n][k]  (transposed at staging)

    const int tid = threadIdx.x;
    const int n0  = blockIdx.x * 64;
    const int m0  = blockIdx.y * 64;
    const int kc  = blockIdx.z;
    const int kbeg = kc * KCHUNK;
    float* out = g_act_part + kc * ACT_SZ;

    // ---- stage A 64(m)x64(k): float4 reads, STS.128 (rows 272B, 16B-aligned)
    #pragma unroll
    for (int p = 0; p < 8; p++) {
        int idx = tid + p * 128;        // 1024 float4
        int r  = idx >> 4;              // m row
        int c4 = idx & 15;              // k group
        float4 v = *(const float4*)(A + (m0 + r) * F_SZ + kbeg + c4 * 4);
        *(float4*)&As[r][c4 * 4] = v;
    }
    // ---- stage B 64(k)x64(n) -> Bt[n][k] (scalar transpose stores)
    #pragma unroll
    for (int p = 0; p < 8; p++) {
        int idx = tid + p * 128;
        int r  = idx >> 4;              // k row
        int c4 = idx & 15;              // n group
        int n  = n0 + c4 * 4;
        float4 v = (n < NCOL) ? *(const float4*)(Bm + (kbeg + r) * NCOL + n)
                              : make_float4(0.f, 0.f, 0.f, 0.f);
        Bt[c4 * 4 + 0][r] = v.x;
        Bt[c4 * 4 + 1][r] = v.y;
        Bt[c4 * 4 + 2][r] = v.z;
        Bt[c4 * 4 + 3][r] = v.w;
    }
    __syncthreads();

    const int w    = tid >> 5;          // warp 0..3 -> m-rows 16w..
    const int lane = tid & 31;
    const int g    = lane >> 2;         // groupID 0..7
    const int t4   = lane & 3;          // threadID_in_group
    const int mw   = w * 16;

    float acc[8][4] = {};               // 8 n-frags x 4 C regs

    #pragma unroll
    for (int ks = 0; ks < 8; ks++) {
        const int k0 = ks * 8;
        // A fragment (PTX m16n8k8 tf32 layout), split hi/lo
        float a0 = As[mw + g    ][k0 + t4    ];
        float a1 = As[mw + g + 8][k0 + t4    ];
        float a2 = As[mw + g    ][k0 + t4 + 4];
        float a3 = As[mw + g + 8][k0 + t4 + 4];
        unsigned ah[4], al[4];
        ah[0] = tf32_hi(a0); al[0] = __float_as_uint(a0 - __uint_as_float(ah[0]));
        ah[1] = tf32_hi(a1); al[1] = __float_as_uint(a1 - __uint_as_float(ah[1]));
        ah[2] = tf32_hi(a2); al[2] = __float_as_uint(a2 - __uint_as_float(ah[2]));
        ah[3] = tf32_hi(a3); al[3] = __float_as_uint(a3 - __uint_as_float(ah[3]));

        #pragma unroll
        for (int nf = 0; nf < 8; nf++) {
            // B fragment: b0=(k=t4, n=g), b1=(k=t4+4, n=g) from Bt[n][k]
            float b0 = Bt[nf * 8 + g][k0 + t4    ];
            float b1 = Bt[nf * 8 + g][k0 + t4 + 4];
            unsigned bh0 = tf32_hi(b0);
            unsigned bh1 = tf32_hi(b1);
            unsigned bl0 = __float_as_uint(b0 - __uint_as_float(bh0));
            unsigned bl1 = __float_as_uint(b1 - __uint_as_float(bh1));
            mma_tf32(acc[nf], ah, bh0, bh1);   // ah*bh
            mma_tf32(acc[nf], ah, bl0, bl1);   // ah*bl
            mma_tf32(acc[nf], al, bh0, bh1);   // al*bh
        }
    }

    // ---- store C: c0/c1 -> (m0+mw+g, n+2t4, +1); c2/c3 -> row+8. STG.64.
    #pragma unroll
    for (int nf = 0; nf < 8; nf++) {
        int n = n0 + nf * 8 + t4 * 2;
        if (n < NCOL) {
            int mA = m0 + mw + g;
            float2 lo = make_float2(acc[nf][0], acc[nf][1]);
            float2 hi = make_float2(acc[nf][2], acc[nf][3]);
            *(float2*)&out[(size_t)mA * NCOL + n]       = lo;
            *(float2*)&out[(size_t)(mA + 8) * NCOL + n] = hi;
        }
    }
}

// ---------------------------------------------------------------------------
// Epilogue: reduce+transpose (blocks 0..399) + ZERO feature region (400..449).
// ---------------------------------------------------------------------------
__global__ __launch_bounds__(256) void epilogue_kernel(float* __restrict__ out) {
    const int bx = blockIdx.x;
    if (bx < 400) {
        __shared__ float t[32][33];
        const int tm0 = (bx & 15) * 32;
        const int tn0 = (bx >> 4) * 32;
        const int c = threadIdx.x & 31;
        const int r = threadIdx.x >> 5;

        #pragma unroll
        for (int q = 0; q < 4; q++) {
            int mi = r * 4 + q;
            int idx = (tm0 + mi) * NCOL + tn0 + c;
            float s = 0.0f;
            #pragma unroll
            for (int p = 0; p < KSPLIT; p++) s += g_act_part[p * ACT_SZ + idx];
            t[mi][c] = s;
        }
        __syncthreads();
        #pragma unroll
        for (int q = 0; q < 4; q++) {
            int ni = r * 4 + q;
            g_act_T[(tn0 + ni) * B_SZ + tm0 + c] = t[c][ni];
        }
    } else {
        int idx = (bx - 400) * 256 + threadIdx.x;    // 50*256 = 12800 exactly
        int b = idx / 25, j = idx - b * 25;
        ((float2*)(out + (size_t)b * OUTW + F_SZ))[j] = make_float2(0.0f, 0.0f);
    }
}

// ---------------------------------------------------------------------------
// Symmetric pairwise (R8 scalar core) + fused x-copy (y == NK).
// grid = (40, 51), block = 128.
// ---------------------------------------------------------------------------
__global__ __launch_bounds__(128) void pairwise_kernel(const float* __restrict__ x,
                                                       float* __restrict__ out) {
    __shared__ float sJ[32][16];
    __shared__ float e_smem[128][33];
    __shared__ float scol[4][32];

    const int k = blockIdx.y;
    const int tid = threadIdx.x;

    if (k == NK) {
        for (int i = blockIdx.x * 128 + tid; i < 131072; i += 40 * 128) {
            int b = i >> 8, j = i & 255;
            ((float2*)(out + (size_t)b * OUTW))[j] =
                ((const float2*)(x + (size_t)b * F_SZ))[j];
        }
        return;
    }

    const int bx   = blockIdx.x;
    const int pair = bx >> 2;
    const int c0   = (bx & 3) * 32;
    const int I = PAIR_I[pair];
    const int J = PAIR_J[pair];

    {
        int d  = tid >> 3;
        int m4 = (tid & 7) * 4;
        float4 v = *(const float4*)(g_act_T + (k * DK + d) * B_SZ + J * 128 + c0 + m4);
        sJ[m4 + 0][d] = v.x;
        sJ[m4 + 1][d] = v.y;
        sJ[m4 + 2][d] = v.z;
        sJ[m4 + 3][d] = v.w;
    }

    float a[16];
    const int rowB = I * 128 + tid;
    #pragma unroll
    for (int d = 0; d < 16; d++)
        a[d] = g_act_T[(k * DK + d) * B_SZ + rowB];
    __syncthreads();

    const bool diag = (I == J);
    float rowAcc = 0.0f;

    #pragma unroll 4
    for (int b2 = 0; b2 < 32; b2++) {
        const float4* vp = (const float4*)sJ[b2];
        float4 v0 = vp[0], v1 = vp[1], v2 = vp[2], v3 = vp[3];
        float p0 = fabsf(a[0]  - v0.x) + fabsf(a[1]  - v0.y)
                 + fabsf(a[2]  - v0.z) + fabsf(a[3]  - v0.w);
        float p1 = fabsf(a[4]  - v1.x) + fabsf(a[5]  - v1.y)
                 + fabsf(a[6]  - v1.z) + fabsf(a[7]  - v1.w);
        float p2 = fabsf(a[8]  - v2.x) + fabsf(a[9]  - v2.y)
                 + fabsf(a[10] - v2.z) + fabsf(a[11] - v2.w);
        float p3 = fabsf(a[12] - v3.x) + fabsf(a[13] - v3.y)
                 + fabsf(a[14] - v3.z) + fabsf(a[15] - v3.w);
        float e = __expf(-((p0 + p1) + (p2 + p3)));
        rowAcc += e;
        if (!diag)
            e_smem[tid][b2] = e;
    }

    float* fbase = out + F_SZ + k;
    atomicAdd(fbase + (size_t)rowB * OUTW, rowAcc);

    if (!diag) {
        __syncthreads();
        const int col = tid & 31;
        const int q   = tid >> 5;
        float cs = 0.0f;
        #pragma unroll 8
        for (int r = 0; r < 32; r++)
            cs += e_smem[q * 32 + r][col];
        scol[q][col] = cs;
        __syncthreads();
        if (tid < 32) {
            float tot = scol[0][tid] + scol[1][tid]
                      + scol[2][tid] + scol[3][tid];
            atomicAdd(fbase + (size_t)(J * 128 + c0 + tid) * OUTW, tot);
        }
    }
}

// ---------------------------------------------------------------------------
extern "C" void kernel_launch(void* const* d_in, const int* in_sizes, int n_in,
                              void* d_out, int out_size) {
    const float* x = (const float*)d_in[0];
    const float* W = (const float*)d_in[1];
    float* out = (float*)d_out;

    dim3 gemm_grid((NCOL + 63) / 64, B_SZ / 64, KSPLIT);   // 13 x 8 x 8
    gemm_kernel<<<gemm_grid, 128>>>(x, W);

    epilogue_kernel<<<450, 256>>>(out);      // reduce_T (400) + zero feat (50)

    dim3 pw_grid(40, NK + 1);                // 40 x 51 (y=50: x-copy)
    pairwise_kernel<<<pw_grid, 128>>>(x, out);
}